// round 2
// baseline (speedup 1.0000x reference)
#include <cuda_runtime.h>
#include <cuda_bf16.h>

// x: [B=32, C=256, W=56, H=56] fp32, contiguous.
// Groups of 4 consecutive channels. Keep elements that equal the group max AND are > 0,
// clamped to max_clamp; zero otherwise.
//
// Geometry in 256-bit (v8 = 8-float) units:
//   spatial plane per channel: 56*56 = 3136 floats = 392 v8 chunks
//   channel stride = 3136 floats
//   groups total = 32 * 64 = 2048
//   threads = 2048 * 392 = 802,816 = 3136 blocks x 256 (exact, no tail)

static constexpr int V8_PER_PLANE  = 392;    // 3136 / 8
static constexpr int FLT_PER_PLANE = 3136;
static constexpr int FLT_PER_GROUP = 4 * FLT_PER_PLANE;  // 12544
static constexpr int TOTAL_THREADS = 2048 * V8_PER_PLANE;

struct F8 { float v[8]; };

__device__ __forceinline__ F8 ldg256(const float* p) {
    F8 r;
    asm volatile("ld.global.v8.f32 {%0,%1,%2,%3,%4,%5,%6,%7}, [%8];"
                 : "=f"(r.v[0]), "=f"(r.v[1]), "=f"(r.v[2]), "=f"(r.v[3]),
                   "=f"(r.v[4]), "=f"(r.v[5]), "=f"(r.v[6]), "=f"(r.v[7])
                 : "l"(p));
    return r;
}

__device__ __forceinline__ void stg256(float* p, const F8& r) {
    asm volatile("st.global.v8.f32 [%0], {%1,%2,%3,%4,%5,%6,%7,%8};"
                 :: "l"(p),
                    "f"(r.v[0]), "f"(r.v[1]), "f"(r.v[2]), "f"(r.v[3]),
                    "f"(r.v[4]), "f"(r.v[5]), "f"(r.v[6]), "f"(r.v[7])
                 : "memory");
}

__global__ __launch_bounds__(256) void CGM_16707422781821_kernel(
    const float* __restrict__ x,
    float* __restrict__ out,
    const float* __restrict__ max_clamp_p)
{
    int idx = blockIdx.x * blockDim.x + threadIdx.x;

    const float mc = __ldg(max_clamp_p);

    // idx -> (group gb, spatial v8 chunk s)
    int gb = idx / V8_PER_PLANE;
    int s  = idx - gb * V8_PER_PLANE;
    long base = (long)gb * FLT_PER_GROUP + (long)s * 8;

    const float* xp = x + base;
    F8 c0 = ldg256(xp);
    F8 c1 = ldg256(xp + FLT_PER_PLANE);
    F8 c2 = ldg256(xp + 2 * FLT_PER_PLANE);
    F8 c3 = ldg256(xp + 3 * FLT_PER_PLANE);

    #pragma unroll
    for (int i = 0; i < 8; i++) {
        float m = fmaxf(fmaxf(c0.v[i], c1.v[i]), fmaxf(c2.v[i], c3.v[i]));
        float cl = fminf(m, mc);                    // clamp applies only to kept (max) entries
        bool pos = (m > 0.0f);
        c0.v[i] = (pos && c0.v[i] == m) ? cl : 0.0f;
        c1.v[i] = (pos && c1.v[i] == m) ? cl : 0.0f;
        c2.v[i] = (pos && c2.v[i] == m) ? cl : 0.0f;
        c3.v[i] = (pos && c3.v[i] == m) ? cl : 0.0f;
    }

    float* op = out + base;
    stg256(op, c0);
    stg256(op + FLT_PER_PLANE, c1);
    stg256(op + 2 * FLT_PER_PLANE, c2);
    stg256(op + 3 * FLT_PER_PLANE, c3);
}

extern "C" void kernel_launch(void* const* d_in, const int* in_sizes, int n_in,
                              void* d_out, int out_size) {
    const float* x = (const float*)d_in[0];
    // d_in[1] = group_size (int32, == 4, baked into geometry)
    const float* max_clamp_p = (const float*)d_in[2];
    float* out = (float*)d_out;

    const int threads = 256;
    const int blocks = TOTAL_THREADS / threads;  // 3136, exact
    CGM_16707422781821_kernel<<<blocks, threads>>>(x, out, max_clamp_p);
}